// round 12
// baseline (speedup 1.0000x reference)
#include <cuda_runtime.h>
#include <cstdint>

// TurboQuantValue: per-row (128 elems) 4-bit min/max quantize + dequantize.
// out[i] = clip(rint((x[i]-vmin)/(vscale+1e-10)),0,15)*vscale + vmin
// vscale = (vmax-vmin)/(15+1e-10)
//
// FINAL converged configuration (best of 11 rounds; re-bench for stability):
//  - one warp = TWO rows, one float4 per thread per row (MLP=2, coalesced 128B)
//  - paired integer REDUX min/max (s32+u32), no monotone-key transforms:
//      float-min = fminf(asfloat(smin), asfloat(umax))   [no-NaN input]
//      float-max = fmaxf(asfloat(smax), asfloat(umin))
//  - .cs streaming hints (one-pass 512MB stream, don't thrash 126MB L2)
//  - 512-thread CTAs (16 warps, 64KB contiguous address range per CTA)
//  - regs capped at 32 (28 achieved)
// Measured: 74.9us kernel = 7.17 TB/s app bytes (~90% of HBM spec) — HBM-bound.

#define WARPS_PER_BLOCK 16
#define ROWS_PER_WARP 2
#define THREADS (WARPS_PER_BLOCK * 32)

__device__ __forceinline__ float4 quant_row(float4 a) {
    float mn = fminf(fminf(a.x, a.y), fminf(a.z, a.w));
    float mx = fmaxf(fmaxf(a.x, a.y), fmaxf(a.z, a.w));

    // warp min: s32-min covers all-positive case, u32-max covers any-negative.
    // warp max symmetric. (Gaussian input: no NaNs.)
    unsigned bmn = __float_as_uint(mn);
    unsigned bmx = __float_as_uint(mx);
    float mn_s = __int_as_float(__reduce_min_sync(0xFFFFFFFFu, (int)bmn));
    float mn_u = __uint_as_float(__reduce_max_sync(0xFFFFFFFFu, bmn));
    float mx_s = __int_as_float(__reduce_max_sync(0xFFFFFFFFu, (int)bmx));
    float mx_u = __uint_as_float(__reduce_min_sync(0xFFFFFFFFu, bmx));
    mn = fminf(mn_s, mn_u);
    mx = fmaxf(mx_s, mx_u);

    float vscale = (mx - mn) / (15.0f + 1e-10f);
    float inv    = 1.0f / (vscale + 1e-10f);   // one IEEE div per row per lane
    float nb     = -mn * inv;

    float4 r;
    float q;
    q = fminf(fmaxf(rintf(fmaf(a.x, inv, nb)), 0.0f), 15.0f);
    r.x = fmaf(q, vscale, mn);
    q = fminf(fmaxf(rintf(fmaf(a.y, inv, nb)), 0.0f), 15.0f);
    r.y = fmaf(q, vscale, mn);
    q = fminf(fmaxf(rintf(fmaf(a.z, inv, nb)), 0.0f), 15.0f);
    r.z = fmaf(q, vscale, mn);
    q = fminf(fmaxf(rintf(fmaf(a.w, inv, nb)), 0.0f), 15.0f);
    r.w = fmaf(q, vscale, mn);
    return r;
}

__global__ __launch_bounds__(THREADS, 4)   // 4 CTAs x 512 thr = 2048 thr/SM, regs<=32
void turboquant_kernel(const float4* __restrict__ in,
                       float4* __restrict__ out,
                       int n_rows)
{
    int warp_in_block = threadIdx.x >> 5;
    int lane = threadIdx.x & 31;
    int row0 = (blockIdx.x * WARPS_PER_BLOCK + warp_in_block) * ROWS_PER_WARP;
    if (row0 >= n_rows) return;

    size_t idx0 = (size_t)row0 * 32 + lane;   // 32 float4 per row

    // front-load both rows (independent streaming LDG.128s, MLP=2)
    float4 a = __ldcs(&in[idx0]);
    float4 b = __ldcs(&in[idx0 + 32]);

    float4 ra = quant_row(a);
    float4 rb = quant_row(b);

    __stcs(&out[idx0],      ra);
    __stcs(&out[idx0 + 32], rb);
}

extern "C" void kernel_launch(void* const* d_in, const int* in_sizes, int n_in,
                              void* d_out, int out_size)
{
    const float4* x = (const float4*)d_in[0];
    float4* out = (float4*)d_out;

    int n_elems = in_sizes[0];          // 67,108,864
    int n_rows = n_elems / 128;         // 524,288

    int rows_per_block = WARPS_PER_BLOCK * ROWS_PER_WARP;          // 32
    int blocks = (n_rows + rows_per_block - 1) / rows_per_block;   // 16384
    turboquant_kernel<<<blocks, THREADS>>>(x, out, n_rows);
}

// round 13
// speedup vs baseline: 1.0232x; 1.0232x over previous
#include <cuda_runtime.h>
#include <cstdint>

// TurboQuantValue: per-row (128 elems) 4-bit min/max quantize + dequantize.
// out[i] = clip(rint((x[i]-vmin)/(vscale+1e-10)),0,15)*vscale + vmin
// vscale = (vmax-vmin)/(15+1e-10)
//
// Converged configuration (final CTA-size grid point: 1024 thr/CTA):
//  - one warp = TWO rows, one float4 per thread per row (MLP=2, coalesced 128B)
//  - paired integer REDUX min/max (s32+u32), no monotone-key transforms:
//      float-min = fminf(asfloat(smin), asfloat(umax))   [no-NaN input]
//      float-max = fmaxf(asfloat(smax), asfloat(umin))
//  - .cs streaming hints (one-pass 512MB stream, don't thrash 126MB L2)
//  - 1024-thread CTAs (32 warps, 128KB contiguous address range per CTA)
//  - regs capped at 32 (28 achieved); no barriers, no smem
// Measured family: kernel 74.7-75.8us = ~7.2 TB/s app bytes (~90% of HBM spec).

#define WARPS_PER_BLOCK 32
#define ROWS_PER_WARP 2
#define THREADS (WARPS_PER_BLOCK * 32)

__device__ __forceinline__ float4 quant_row(float4 a) {
    float mn = fminf(fminf(a.x, a.y), fminf(a.z, a.w));
    float mx = fmaxf(fmaxf(a.x, a.y), fmaxf(a.z, a.w));

    // warp min: s32-min covers all-positive case, u32-max covers any-negative.
    // warp max symmetric. (Gaussian input: no NaNs.)
    unsigned bmn = __float_as_uint(mn);
    unsigned bmx = __float_as_uint(mx);
    float mn_s = __int_as_float(__reduce_min_sync(0xFFFFFFFFu, (int)bmn));
    float mn_u = __uint_as_float(__reduce_max_sync(0xFFFFFFFFu, bmn));
    float mx_s = __int_as_float(__reduce_max_sync(0xFFFFFFFFu, (int)bmx));
    float mx_u = __uint_as_float(__reduce_min_sync(0xFFFFFFFFu, bmx));
    mn = fminf(mn_s, mn_u);
    mx = fmaxf(mx_s, mx_u);

    float vscale = (mx - mn) / (15.0f + 1e-10f);
    float inv    = 1.0f / (vscale + 1e-10f);   // one IEEE div per row per lane
    float nb     = -mn * inv;

    float4 r;
    float q;
    q = fminf(fmaxf(rintf(fmaf(a.x, inv, nb)), 0.0f), 15.0f);
    r.x = fmaf(q, vscale, mn);
    q = fminf(fmaxf(rintf(fmaf(a.y, inv, nb)), 0.0f), 15.0f);
    r.y = fmaf(q, vscale, mn);
    q = fminf(fmaxf(rintf(fmaf(a.z, inv, nb)), 0.0f), 15.0f);
    r.z = fmaf(q, vscale, mn);
    q = fminf(fmaxf(rintf(fmaf(a.w, inv, nb)), 0.0f), 15.0f);
    r.w = fmaf(q, vscale, mn);
    return r;
}

__global__ __launch_bounds__(THREADS, 2)   // 2 CTAs x 1024 thr = 2048 thr/SM, regs<=32
void turboquant_kernel(const float4* __restrict__ in,
                       float4* __restrict__ out,
                       int n_rows)
{
    int warp_in_block = threadIdx.x >> 5;
    int lane = threadIdx.x & 31;
    int row0 = (blockIdx.x * WARPS_PER_BLOCK + warp_in_block) * ROWS_PER_WARP;
    if (row0 >= n_rows) return;

    size_t idx0 = (size_t)row0 * 32 + lane;   // 32 float4 per row

    // front-load both rows (independent streaming LDG.128s, MLP=2)
    float4 a = __ldcs(&in[idx0]);
    float4 b = __ldcs(&in[idx0 + 32]);

    float4 ra = quant_row(a);
    float4 rb = quant_row(b);

    __stcs(&out[idx0],      ra);
    __stcs(&out[idx0 + 32], rb);
}

extern "C" void kernel_launch(void* const* d_in, const int* in_sizes, int n_in,
                              void* d_out, int out_size)
{
    const float4* x = (const float4*)d_in[0];
    float4* out = (float4*)d_out;

    int n_elems = in_sizes[0];          // 67,108,864
    int n_rows = n_elems / 128;         // 524,288

    int rows_per_block = WARPS_PER_BLOCK * ROWS_PER_WARP;          // 64
    int blocks = (n_rows + rows_per_block - 1) / rows_per_block;   // 8192
    turboquant_kernel<<<blocks, THREADS>>>(x, out, n_rows);
}